// round 16
// baseline (speedup 1.0000x reference)
#include <cuda_runtime.h>

// ESH sampler: B rows, D=64, n_steps of 2 half-steps each.
// Layout: 8 lanes per row (group), 4 rows per warp, 8 warps/CTA, 4 CTAs/SM
// (the measured-optimal 32 warps/SM). Lane-in-group p owns float4 chunks {p, p+8}.
//
// f32x2 packed math (PTX-only on sm_103a). Grad reused across the step
// boundary. After the drift, the gsq (new x) and ugr (u.g) shuffle-reduction
// trees are INTERLEAVED — independent chains overlap their SHFL latency,
// removing one serial ~80-cycle reduction per step from the warp's critical
// path. Stores use st.global.wt (write-once data, never re-read).

using u64t = unsigned long long;

__device__ __forceinline__ u64t mul2(u64t a, u64t b) {
    u64t d; asm("mul.rn.f32x2 %0, %1, %2;" : "=l"(d) : "l"(a), "l"(b)); return d;
}
__device__ __forceinline__ u64t fma2(u64t a, u64t b, u64t c) {
    u64t d; asm("fma.rn.f32x2 %0, %1, %2, %3;" : "=l"(d) : "l"(a), "l"(b), "l"(c)); return d;
}
__device__ __forceinline__ u64t pack2(float lo, float hi) {
    u64t d; asm("mov.b64 %0, {%1, %2};" : "=l"(d) : "f"(lo), "f"(hi)); return d;
}
__device__ __forceinline__ float2 unpack2(u64t q) {
    float lo, hi; asm("mov.b64 {%0, %1}, %2;" : "=f"(lo), "=f"(hi) : "l"(q));
    return make_float2(lo, hi);
}

union Q2F { ulonglong2 q; float4 f; };

__device__ __forceinline__ float grp_sum8(float v) {
    v += __shfl_xor_sync(0xffffffffu, v, 1);
    v += __shfl_xor_sync(0xffffffffu, v, 2);
    v += __shfl_xor_sync(0xffffffffu, v, 4);
    return v;
}

// Two independent group reductions with interleaved shuffle chains.
__device__ __forceinline__ void grp_sum8_x2(float& a, float& b) {
    float a1 = __shfl_xor_sync(0xffffffffu, a, 1);
    float b1 = __shfl_xor_sync(0xffffffffu, b, 1);
    a += a1; b += b1;
    float a2 = __shfl_xor_sync(0xffffffffu, a, 2);
    float b2 = __shfl_xor_sync(0xffffffffu, b, 2);
    a += a2; b += b2;
    float a4 = __shfl_xor_sync(0xffffffffu, a, 4);
    float b4 = __shfl_xor_sync(0xffffffffu, b, 4);
    a += a4; b += b4;
}

// Scalars that depend only on gsq.
__device__ __forceinline__ void g_scalars(
    float gsq, float& rs, float& gn, float& t2, float& Bc, float ed)
{
    rs = rsqrtf(fmaxf(gsq, 1e-20f));     // == 1/||g||
    gn = fminf(gsq * rs, 10.0f);         // clamped norm
    float t = __expf(-ed * gn);          // exp(-e*g/d)
    t2 = t * t;
    Bc = 2.0f * t;
}

// Momentum/r update given precomputed g, scalars, and ALREADY-REDUCED ugr.
__device__ __forceinline__ void update_ur_body(
    const u64t (&gq)[4], u64t (&uq)[4], float ugr,
    float& us, float& r, float rs, float gn, float t2, float Bc, float ed)
{
    float ude  = -(us * ugr) * rs;            // u_true . grad_e
    float A2   = (ude - 1.0f) * t2;
    float opu  = 1.0f + ude;
    float A    = opu + A2;
    bool  cond = ude > -0.999f;
    float Bs   = cond ? Bc * us : 0.0f;                  // coeff on u_raw
    float Cc   = cond ? fmaf(Bc, ude, -A) * rs : rs;     // coeff on g

    u64t bs2 = pack2(Bs, Bs);
    u64t cc2 = pack2(Cc, Cc);
    u64t nsq2 = 0ull;
#pragma unroll
    for (int k = 0; k < 4; k++) {
        u64t un = fma2(cc2, gq[k], mul2(bs2, uq[k]));
        uq[k] = un;
        nsq2 = fma2(un, un, nsq2);
    }
    float2 sn = unpack2(nsq2);
    float nsq = grp_sum8(sn.x + sn.y);
    us = rsqrtf(fmaxf(nsq, 1e-20f));          // u_true = us * u_raw

    float Z  = opu - A2;
    float dr = cond ? fmaf(ed, gn, __logf(0.5f * fmaxf(Z, 1e-10f)))
                    : -ed * gn;
    r += dr;
}

__global__ __launch_bounds__(256, 4)
void esh_kernel(const float* __restrict__ x0,
                const float* __restrict__ u0,
                const float* __restrict__ prec,
                const float* __restrict__ eps_p,
                const int* __restrict__ nsteps_p,
                float* __restrict__ out,
                int B)
{
    const int tid  = threadIdx.x;
    const int lane = tid & 31;
    const int p    = lane & 7;       // lane within group (8 per row)
    const int grp  = lane >> 3;      // 0..3 : row within warp
    const int warp = tid >> 5;       // 0..7
    const int row  = blockIdx.x * 32 + warp * 4 + grp;
    if (row >= B) return;

    const float eps = *eps_p;
    const int n_steps = *nsteps_p;
    const float ed = (0.5f * eps) * (1.0f / 64.0f);  // e/d, e = eps/2

    // state: 8 floats/lane per array = 4 packed f32x2 regs
    u64t xq[4], uq[4], pq[4];
    {
        const ulonglong2* xp = reinterpret_cast<const ulonglong2*>(x0 + (size_t)row * 64);
        const ulonglong2* up = reinterpret_cast<const ulonglong2*>(u0 + (size_t)row * 64);
        const ulonglong2* pp = reinterpret_cast<const ulonglong2*>(prec);
#pragma unroll
        for (int j = 0; j < 2; j++) {
            ulonglong2 a = xp[p + 8 * j]; xq[2 * j] = a.x; xq[2 * j + 1] = a.y;
            ulonglong2 b = up[p + 8 * j]; uq[2 * j] = b.x; uq[2 * j + 1] = b.y;
            ulonglong2 c = pp[p + 8 * j]; pq[2 * j] = c.x; pq[2 * j + 1] = c.y;
        }
    }
    float r = 0.0f;
    float us = 1.0f;   // u_true = us * uq

    const size_t rowstride = (size_t)B * 64;
    const size_t XN = (size_t)(n_steps + 1) * rowstride;
    float* outr = out + 2 * XN + row;

    float4* ox = reinterpret_cast<float4*>(out + (size_t)row * 64);
    float4* ou = reinterpret_cast<float4*>(out + XN + (size_t)row * 64);

    // step 0: x0, u0, r0=0
#pragma unroll
    for (int j = 0; j < 2; j++) {
        Q2F tx; tx.q.x = xq[2 * j]; tx.q.y = xq[2 * j + 1];
        Q2F tu; tu.q.x = uq[2 * j]; tu.q.y = uq[2 * j + 1];
        __stwt(&ox[p + 8 * j], tx.f);
        __stwt(&ou[p + 8 * j], tu.f);
    }
    if (p == 0) __stwt(outr, 0.0f);

    const size_t f4stride = rowstride / 4;  // float4 elements per step

    // prologue: gradient at x0 (reused by step 1's first half-step)
    u64t gq[4];
    float rs, gn, t2, Bc;
    {
        u64t gsq2 = 0ull;
#pragma unroll
        for (int k = 0; k < 4; k++) {
            gq[k] = mul2(pq[k], xq[k]);
            gsq2  = fma2(gq[k], gq[k], gsq2);
        }
        float2 s = unpack2(gsq2);
        float gsq = grp_sum8(s.x + s.y);
        g_scalars(gsq, rs, gn, t2, Bc, ed);
    }

    for (int s = 1; s <= n_steps; s++) {
        // first half-step: g carried over; reduce u.g alone
        {
            u64t ug2 = 0ull;
#pragma unroll
            for (int k = 0; k < 4; k++) ug2 = fma2(uq[k], gq[k], ug2);
            float2 su = unpack2(ug2);
            float ugr = grp_sum8(su.x + su.y);
            update_ur_body(gq, uq, ugr, us, r, rs, gn, t2, Bc, ed);
        }

        // drift: x += eps * u_true ; x final for this step -> store now
        {
            const float c = eps * us;
            const u64t c2 = pack2(c, c);
#pragma unroll
            for (int k = 0; k < 4; k++) xq[k] = fma2(c2, uq[k], xq[k]);
        }
        ox += f4stride;
#pragma unroll
        for (int j = 0; j < 2; j++) {
            Q2F tx; tx.q.x = xq[2 * j]; tx.q.y = xq[2 * j + 1];
            __stwt(&ox[p + 8 * j], tx.f);
        }

        // merged: gradient at drifted x AND u.g — interleaved reduction chains
        float ugr2;
        {
            u64t gsq2 = 0ull, ug2 = 0ull;
#pragma unroll
            for (int k = 0; k < 4; k++) {
                gq[k] = mul2(pq[k], xq[k]);
                gsq2  = fma2(gq[k], gq[k], gsq2);
                ug2   = fma2(uq[k], gq[k], ug2);
            }
            float2 sg = unpack2(gsq2);
            float2 su = unpack2(ug2);
            float gsq = sg.x + sg.y;
            ugr2 = su.x + su.y;
            grp_sum8_x2(gsq, ugr2);
            g_scalars(gsq, rs, gn, t2, Bc, ed);
        }

        // second half-step (g also serves next iteration's first half-step)
        update_ur_body(gq, uq, ugr2, us, r, rs, gn, t2, Bc, ed);

        ou += f4stride;
        outr += B;
        // materialize normalized u and store
        {
            const u64t us2 = pack2(us, us);
#pragma unroll
            for (int k = 0; k < 4; k++) uq[k] = mul2(uq[k], us2);
#pragma unroll
            for (int j = 0; j < 2; j++) {
                Q2F tu; tu.q.x = uq[2 * j]; tu.q.y = uq[2 * j + 1];
                __stwt(&ou[p + 8 * j], tu.f);
            }
        }
        us = 1.0f;
        if (p == 0) __stwt(outr, r);
    }
}

extern "C" void kernel_launch(void* const* d_in, const int* in_sizes, int n_in,
                              void* d_out, int out_size)
{
    const float* x0     = (const float*)d_in[0];
    const float* u0     = (const float*)d_in[1];
    const float* prec   = (const float*)d_in[2];
    const float* eps_p  = (const float*)d_in[3];
    const int*   nsteps = (const int*)d_in[4];
    float* out = (float*)d_out;

    int B = in_sizes[0] / 64;
    int rows_per_block = 32;  // 256 threads, 8 warps, 4 rows/warp
    int grid = (B + rows_per_block - 1) / rows_per_block;
    esh_kernel<<<grid, 256>>>(x0, u0, prec, eps_p, nsteps, out, B);
}